// round 8
// baseline (speedup 1.0000x reference)
#include <cuda_runtime.h>
#include <cuda_bf16.h>
#include <math.h>
#include <stdint.h>

// ---------------------------------------------------------------------------
// MMD^2 (RBF, gamma=1), 8192x16 fp32, via mma.sync.m16n8k16 bf16 (sm_100 base).
//
// Coords scaled by sqrt(2*log2e), split x = hi + mid (bf16).
// A row: [hi(16) mid(16) hi(16) mid(16) | nh nm nl 1 1 1 | 0...]   (80 used)
// B row: [hi(16) hi(16) mid(16) mid(16) | 1 1 1 nh nm nl | 0...]
// => GEMM output D = -log2e*||a-b||^2; per-pair value = ex2(D).
// Only the tile SUM is needed -> fragment mapping irrelevant.
// n-dim split into two halves per warp; half-B's mainloop interleaves
// half-A's MUFU epilogue so tensor and MUFU pipes overlap in-warp.
// ---------------------------------------------------------------------------

#define NSRC   8192
#define D      16
#define NP     16384
#define TILE   128
#define TB     (NP / TILE)                 // 128
#define NBLK   (TB * (TB + 1) / 2)         // 8256
#define SQ2L   1.6986436004918308f         // sqrt(2*log2(e))
#define KPAD   88
#define ROWB   (KPAD * 2)                  // 176 B per row
#define NKC    5                           // K chunks of 16 (cols 0..79)
#define ATILEB (TILE * ROWB)               // 22528 B per tile side

// per point: u0,u1 = hi(16 bf16), u2,u3 = mid, u4 = normA unit, u5 = normB unit
__device__ uint4  g_S[NP * 6];
__device__ double g_part[NBLK];

// ---------------- helpers ----------------
__device__ __forceinline__ float ex2(float x) {
    float r; asm("ex2.approx.f32 %0, %1;" : "=f"(r) : "f"(x)); return r;
}
__device__ __forceinline__ uint32_t smem_u32(const void* p) {
    uint32_t a;
    asm("{ .reg .u64 t; cvta.to.shared.u64 t, %1; cvt.u32.u64 %0, t; }"
        : "=r"(a) : "l"(p));
    return a;
}
__device__ __forceinline__ void ldsm4(uint32_t* r, uint32_t addr) {
    asm volatile("ldmatrix.sync.aligned.m8n8.x4.shared.b16 {%0,%1,%2,%3}, [%4];"
                 : "=r"(r[0]), "=r"(r[1]), "=r"(r[2]), "=r"(r[3]) : "r"(addr));
}
__device__ __forceinline__ void mma16816(float* c, const uint32_t* a,
                                         uint32_t b0, uint32_t b1) {
    asm volatile("mma.sync.aligned.m16n8k16.row.col.f32.bf16.bf16.f32 "
                 "{%0,%1,%2,%3}, {%4,%5,%6,%7}, {%8,%9}, {%0,%1,%2,%3};"
                 : "+f"(c[0]), "+f"(c[1]), "+f"(c[2]), "+f"(c[3])
                 : "r"(a[0]), "r"(a[1]), "r"(a[2]), "r"(a[3]), "r"(b0), "r"(b1));
}
__device__ __forceinline__ int tri_row_start(int t) {
    return t * TB - ((t * (t - 1)) >> 1);
}

// ---------------------------------------------------------------------------
// Kernel 1: scale, hi/mid split, 3-way-split norm units.
// ---------------------------------------------------------------------------
__global__ void __launch_bounds__(256) split_kernel(const float* __restrict__ src,
                                                    const float* __restrict__ tgt) {
    int p = blockIdx.x * 256 + threadIdx.x;
    if (p >= NP) return;
    const float* x = (p < NSRC) ? (src + (size_t)p * D) : (tgt + (size_t)(p - NSRC) * D);

    uint4 u[6];
    __nv_bfloat16* hi  = (__nv_bfloat16*)&u[0];
    __nv_bfloat16* mid = (__nv_bfloat16*)&u[2];
    __nv_bfloat16* nA  = (__nv_bfloat16*)&u[4];
    __nv_bfloat16* nB  = (__nv_bfloat16*)&u[5];

    float ns = 0.f;
#pragma unroll
    for (int d = 0; d < D; d++) {
        float v = x[d] * SQ2L;
        ns = fmaf(v, v, ns);
        __nv_bfloat16 h = __float2bfloat16(v);
        float r1 = v - __bfloat162float(h);
        hi[d]  = h;
        mid[d] = __float2bfloat16(r1);
    }
    float na = -0.5f * ns;
    __nv_bfloat16 nh = __float2bfloat16(na);
    float nr1 = na - __bfloat162float(nh);
    __nv_bfloat16 nm = __float2bfloat16(nr1);
    __nv_bfloat16 nl = __float2bfloat16(nr1 - __bfloat162float(nm));
    const __nv_bfloat16 one  = __float2bfloat16(1.0f);
    const __nv_bfloat16 zero = __float2bfloat16(0.0f);

    nA[0] = nh;  nA[1] = nm;  nA[2] = nl;  nA[3] = one; nA[4] = one; nA[5] = one;
    nA[6] = zero; nA[7] = zero;
    nB[0] = one; nB[1] = one; nB[2] = one; nB[3] = nh;  nB[4] = nm;  nB[5] = nl;
    nB[6] = zero; nB[7] = zero;

    uint4* out = g_S + (size_t)p * 6;
#pragma unroll
    for (int i = 0; i < 6; i++) out[i] = u[i];
}

// ---------------------------------------------------------------------------
// Kernel 2: pairwise 128x128 tiles, two n-halves with interleaved epilogue.
// Warp w: rows (w&3)*32 + {0,16}, cols (w>>2)*64.
// ---------------------------------------------------------------------------
__global__ void __launch_bounds__(256, 2) pair_kernel() {
    extern __shared__ __align__(16) char dsm[];
    __shared__ float wsum[8];

    const int bid  = blockIdx.x;
    const int tid  = threadIdx.x;
    const int lane = tid & 31;
    const int w    = tid >> 5;

    int ti = (int)((2.0 * TB + 1.0 - sqrt((2.0 * TB + 1.0) * (2.0 * TB + 1.0)
                                          - 8.0 * (double)bid)) * 0.5);
    while (tri_row_start(ti + 1) <= bid) ti++;
    while (tri_row_start(ti) > bid) ti--;
    const int tj = ti + (bid - tri_row_start(ti));

    // ---- build A/B tiles in SMEM (row stride 176B) ----
    {
        const int  row = tid & 127;
        const bool isA = tid < 128;
        const uint4* srow = g_S + (size_t)(((isA ? ti : tj) * TILE) + row) * 6;
        char* rbase = dsm + (isA ? 0 : ATILEB) + row * ROWB;

        uint4 u[6];
#pragma unroll
        for (int i = 0; i < 6; i++) u[i] = srow[i];

        const int mapA[11] = {0,1, 2,3, 0,1, 2,3, 4, -1, -1};
        const int mapB[11] = {0,1, 0,1, 2,3, 2,3, 5, -1, -1};
#pragma unroll
        for (int c = 0; c < 11; c++) {
            int s = isA ? mapA[c] : mapB[c];
            uint4 v = (s >= 0) ? u[s] : make_uint4(0u, 0u, 0u, 0u);
            *(uint4*)(rbase + c * 16) = v;
        }
    }
    __syncthreads();

    const uint32_t sA = smem_u32(dsm);
    const uint32_t sB = sA + ATILEB;
    const int mbase = (w & 3) * 32;
    const int nbase = (w >> 2) * 64;

    // ---- preload all A fragments (shared by both halves) ----
    const uint32_t aRow   = (uint32_t)(mbase + (lane & 7) + ((lane >> 3) & 1) * 8);
    const uint32_t aAddr0 = sA + aRow * ROWB + ((lane >> 4) & 1) * 16;
    const uint32_t aAddr1 = aAddr0 + 16 * ROWB;
    uint32_t a0[NKC][4], a1[NKC][4];
#pragma unroll
    for (int kc = 0; kc < NKC; kc++) {
        ldsm4(a0[kc], aAddr0 + kc * 32);
        ldsm4(a1[kc], aAddr1 + kc * 32);
    }

    const uint32_t bRowQ = (uint32_t)((lane & 7) + ((lane >> 4) & 1) * 8);
    const uint32_t bColH = ((lane >> 3) & 1) * 16;
    const uint32_t bBase = sB + (uint32_t)(nbase + bRowQ) * ROWB + bColH;
    // q-group base address offset: 16 rows * ROWB per q
    // accA/accB flat layout: group g = ((mt*2)+q)*2+h, elems g*4..g*4+3

    float accA[32], accB[32];
#pragma unroll
    for (int i = 0; i < 32; i++) { accA[i] = 0.f; accB[i] = 0.f; }

    // ================= phase 1: half A mainloop (q = 0,1) =================
#pragma unroll
    for (int kc = 0; kc < NKC; kc++) {
        uint32_t b0[4], b1[4];
        ldsm4(b0, bBase + 0 * 16 * ROWB + kc * 32);
        ldsm4(b1, bBase + 1 * 16 * ROWB + kc * 32);
        mma16816(accA + 0,  a0[kc], b0[0], b0[1]);
        mma16816(accA + 4,  a0[kc], b0[2], b0[3]);
        mma16816(accA + 8,  a0[kc], b1[0], b1[1]);
        mma16816(accA + 12, a0[kc], b1[2], b1[3]);
        mma16816(accA + 16, a1[kc], b0[0], b0[1]);
        mma16816(accA + 20, a1[kc], b0[2], b0[3]);
        mma16816(accA + 24, a1[kc], b1[0], b1[1]);
        mma16816(accA + 28, a1[kc], b1[2], b1[3]);
    }

    // ====== phase 2: half B mainloop (q = 2,3) + half-A MUFU epilogue ======
    float s0 = 0.f, s1 = 0.f, s2 = 0.f, s3 = 0.f;
    {
        const int ES[NKC + 1] = {0, 7, 14, 20, 26, 32};   // ex2 schedule
#pragma unroll
        for (int kc = 0; kc < NKC; kc++) {
            uint32_t b2[4], b3[4];
            ldsm4(b2, bBase + 2 * 16 * ROWB + kc * 32);
            ldsm4(b3, bBase + 3 * 16 * ROWB + kc * 32);
            mma16816(accB + 0,  a0[kc], b2[0], b2[1]);
            mma16816(accB + 4,  a0[kc], b2[2], b2[3]);
            mma16816(accB + 8,  a0[kc], b3[0], b3[1]);
            mma16816(accB + 12, a0[kc], b3[2], b3[3]);
            mma16816(accB + 16, a1[kc], b2[0], b2[1]);
            mma16816(accB + 20, a1[kc], b2[2], b2[3]);
            mma16816(accB + 24, a1[kc], b3[0], b3[1]);
            mma16816(accB + 28, a1[kc], b3[2], b3[3]);
            // interleaved MUFU work on finished half-A accumulators
#pragma unroll
            for (int t = ES[kc]; t < ES[kc + 1]; t++) {
                float e = ex2(accA[t]);
                if      ((t & 3) == 0) s0 += e;
                else if ((t & 3) == 1) s1 += e;
                else if ((t & 3) == 2) s2 += e;
                else                   s3 += e;
            }
        }
    }

    // ================= phase 3: half B epilogue tail =================
#pragma unroll
    for (int t = 0; t < 32; t += 4) {
        s0 += ex2(accB[t + 0]);
        s1 += ex2(accB[t + 1]);
        s2 += ex2(accB[t + 2]);
        s3 += ex2(accB[t + 3]);
    }

    float tsum = (s0 + s1) + (s2 + s3);
#pragma unroll
    for (int off = 16; off; off >>= 1)
        tsum += __shfl_xor_sync(0xffffffffu, tsum, off);
    if (lane == 0) wsum[w] = tsum;
    __syncthreads();

    if (tid == 0) {
        double t = 0.0;
#pragma unroll
        for (int x = 0; x < 8; x++) t += (double)wsum[x];
        double wgt = (ti == tj) ? 1.0 : 2.0;
        double sgn = ((ti < TB / 2) == (tj < TB / 2)) ? 1.0 : -1.0;
        g_part[bid] = t * wgt * sgn;
    }
}

// ---------------------------------------------------------------------------
// Kernel 3: fixed-order double reduction -> scalar
// ---------------------------------------------------------------------------
__global__ void __launch_bounds__(512) finish_kernel(float* out) {
    __shared__ double s[512];
    const int tid = threadIdx.x;
    const double2* p2 = (const double2*)g_part;       // NBLK even
    double t0 = 0.0, t1 = 0.0;
#pragma unroll 4
    for (int i = tid; i < NBLK / 2; i += 512) {
        double2 v = p2[i];
        t0 += v.x;
        t1 += v.y;
    }
    s[tid] = t0 + t1;
    __syncthreads();
#pragma unroll
    for (int off = 256; off; off >>= 1) {
        if (tid < off) s[tid] += s[tid + off];
        __syncthreads();
    }
    if (tid == 0) out[0] = (float)(s[0] / 67108864.0);   // / n^2, n = 8192
}

// ---------------------------------------------------------------------------
extern "C" void kernel_launch(void* const* d_in, const int* in_sizes, int n_in,
                              void* d_out, int out_size) {
    const float* src = (const float*)d_in[0];
    const float* tgt = (const float*)d_in[1];

    const int smem_bytes = 2 * ATILEB;     // 45056 B
    cudaFuncSetAttribute(pair_kernel, cudaFuncAttributeMaxDynamicSharedMemorySize,
                         smem_bytes);

    split_kernel<<<(NP + 255) / 256, 256>>>(src, tgt);
    pair_kernel<<<NBLK, 256, smem_bytes>>>();
    finish_kernel<<<1, 512>>>((float*)d_out);
}

// round 9
// speedup vs baseline: 2.1628x; 2.1628x over previous
#include <cuda_runtime.h>
#include <cuda_fp16.h>
#include <math.h>
#include <stdint.h>

// ---------------------------------------------------------------------------
// MMD^2 (RBF, gamma=1), 8192x16 fp32, via mma.sync.m16n8k16 fp16 (sm_100 base).
//
// Coords scaled by sqrt(2*log2e), split x = hi + lo (fp16, 11-bit mantissa:
// residual ~2^-22 relative -> lo*lo term negligible).
// A row k16-chunks: [hi | lo | hi | nA]   (64 cols, 128B, rows padded to 144B)
// B row k16-chunks: [hi | hi | lo | nB]
//   nA = [na_hi na_lo 1 1 0...], nB = [1 1 nb_hi nb_lo 0...], na = -0.5|a|^2
// => GEMM output D = dot(a,b) - 0.5|a|^2 - 0.5|b|^2 = -log2e*||a-b||^2_orig.
// Per-pair value = ex2(D); only the tile SUM is needed -> fragment mapping
// irrelevant. Upper-triangle 128x128 tiles, weight 2 off-diagonal.
// ---------------------------------------------------------------------------

#define NSRC   8192
#define D      16
#define NP     16384
#define TILE   128
#define TB     (NP / TILE)                 // 128
#define NBLK   (TB * (TB + 1) / 2)         // 8256
#define SQ2L   1.6986436004918308f         // sqrt(2*log2(e))
#define ROWB   144                         // 128B data + 16B pad (conflict-free)
#define NKC    4                           // K = 64, chunks of 16
#define ATILEB (TILE * ROWB)               // 18432 B per tile side

// per point: u0,u1 = hi(16 fp16), u2,u3 = lo, u4 = normA unit, u5 = normB unit
__device__ uint4  g_S[NP * 6];
__device__ double g_part[NBLK];

// ---------------- helpers ----------------
__device__ __forceinline__ float ex2(float x) {
    float r; asm("ex2.approx.f32 %0, %1;" : "=f"(r) : "f"(x)); return r;
}
__device__ __forceinline__ uint32_t smem_u32(const void* p) {
    uint32_t a;
    asm("{ .reg .u64 t; cvta.to.shared.u64 t, %1; cvt.u32.u64 %0, t; }"
        : "=r"(a) : "l"(p));
    return a;
}
__device__ __forceinline__ void ldsm4(uint32_t* r, uint32_t addr) {
    asm volatile("ldmatrix.sync.aligned.m8n8.x4.shared.b16 {%0,%1,%2,%3}, [%4];"
                 : "=r"(r[0]), "=r"(r[1]), "=r"(r[2]), "=r"(r[3]) : "r"(addr));
}
__device__ __forceinline__ void mma16816(float* c, const uint32_t* a,
                                         uint32_t b0, uint32_t b1) {
    asm volatile("mma.sync.aligned.m16n8k16.row.col.f32.f16.f16.f32 "
                 "{%0,%1,%2,%3}, {%4,%5,%6,%7}, {%8,%9}, {%0,%1,%2,%3};"
                 : "+f"(c[0]), "+f"(c[1]), "+f"(c[2]), "+f"(c[3])
                 : "r"(a[0]), "r"(a[1]), "r"(a[2]), "r"(a[3]), "r"(b0), "r"(b1));
}
__device__ __forceinline__ int tri_row_start(int t) {
    return t * TB - ((t * (t - 1)) >> 1);
}

// ---------------------------------------------------------------------------
// Kernel 1: scale, fp16 hi/lo split, 2-split norm units.
// ---------------------------------------------------------------------------
__global__ void __launch_bounds__(256) split_kernel(const float* __restrict__ src,
                                                    const float* __restrict__ tgt) {
    int p = blockIdx.x * 256 + threadIdx.x;
    if (p >= NP) return;
    const float* x = (p < NSRC) ? (src + (size_t)p * D) : (tgt + (size_t)(p - NSRC) * D);

    uint4 u[6];
    __half* hi = (__half*)&u[0];
    __half* lo = (__half*)&u[2];
    __half* nA = (__half*)&u[4];
    __half* nB = (__half*)&u[5];

    float ns = 0.f;
#pragma unroll
    for (int d = 0; d < D; d++) {
        float v = x[d] * SQ2L;
        ns = fmaf(v, v, ns);
        __half h = __float2half_rn(v);
        hi[d] = h;
        lo[d] = __float2half_rn(v - __half2float(h));
    }
    float na = -0.5f * ns;
    __half nh = __float2half_rn(na);
    __half nl = __float2half_rn(na - __half2float(nh));
    const __half one  = __float2half_rn(1.0f);
    const __half zero = __float2half_rn(0.0f);

    nA[0] = nh;  nA[1] = nl;  nA[2] = one; nA[3] = one;
    nA[4] = zero; nA[5] = zero; nA[6] = zero; nA[7] = zero;
    nB[0] = one; nB[1] = one; nB[2] = nh;  nB[3] = nl;
    nB[4] = zero; nB[5] = zero; nB[6] = zero; nB[7] = zero;

    uint4* out = g_S + (size_t)p * 6;
#pragma unroll
    for (int i = 0; i < 6; i++) out[i] = u[i];
}

// ---------------------------------------------------------------------------
// Kernel 2: pairwise 128x128 tiles via fp16 mma.sync (R6 structure, K=64).
// Warp w: rows (w&3)*32 + {0,16}, cols (w>>2)*64 (8 n8-tiles).
// ---------------------------------------------------------------------------
__global__ void __launch_bounds__(256, 2) pair_kernel() {
    extern __shared__ __align__(16) char dsm[];
    __shared__ float wsum[8];

    const int bid  = blockIdx.x;
    const int tid  = threadIdx.x;
    const int lane = tid & 31;
    const int w    = tid >> 5;

    int ti = (int)((2.0 * TB + 1.0 - sqrt((2.0 * TB + 1.0) * (2.0 * TB + 1.0)
                                          - 8.0 * (double)bid)) * 0.5);
    while (tri_row_start(ti + 1) <= bid) ti++;
    while (tri_row_start(ti) > bid) ti--;
    const int tj = ti + (bid - tri_row_start(ti));

    // ---- build A/B tiles in SMEM (row stride 144B; conflict-free ldmatrix) ----
    {
        const int  row = tid & 127;
        const bool isA = tid < 128;
        const uint4* srow = g_S + (size_t)(((isA ? ti : tj) * TILE) + row) * 6;
        char* rbase = dsm + (isA ? 0 : ATILEB) + row * ROWB;

        uint4 u[6];
#pragma unroll
        for (int i = 0; i < 6; i++) u[i] = srow[i];

        // 16B chunk units per row (8 = 128B of K data):
        // A: [hi hi lo lo hi hi nA 0]
        // B: [hi hi hi hi lo lo nB 0]
        const int mapA[8] = {0,1, 2,3, 0,1, 4, -1};
        const int mapB[8] = {0,1, 0,1, 2,3, 5, -1};
#pragma unroll
        for (int c = 0; c < 8; c++) {
            int s = isA ? mapA[c] : mapB[c];
            uint4 v = (s >= 0) ? u[s] : make_uint4(0u, 0u, 0u, 0u);
            *(uint4*)(rbase + c * 16) = v;
        }
    }
    __syncthreads();

    const uint32_t sA = smem_u32(dsm);
    const uint32_t sB = sA + ATILEB;
    const int mbase = (w & 3) * 32;
    const int nbase = (w >> 2) * 64;

    // ---- preload all A fragments (4 kc x 2 m-tiles = 32 regs) ----
    const uint32_t aRow   = (uint32_t)(mbase + (lane & 7) + ((lane >> 3) & 1) * 8);
    const uint32_t aAddr0 = sA + aRow * ROWB + ((lane >> 4) & 1) * 16;
    const uint32_t aAddr1 = aAddr0 + 16 * ROWB;
    uint32_t a0[NKC][4], a1[NKC][4];
#pragma unroll
    for (int kc = 0; kc < NKC; kc++) {
        ldsm4(a0[kc], aAddr0 + kc * 32);
        ldsm4(a1[kc], aAddr1 + kc * 32);
    }

    const uint32_t bRowQ = (uint32_t)((lane & 7) + ((lane >> 4) & 1) * 8);
    const uint32_t bColH = ((lane >> 3) & 1) * 16;
    uint32_t bAddr[4];
#pragma unroll
    for (int q = 0; q < 4; q++)
        bAddr[q] = sB + (uint32_t)(nbase + 16 * q + bRowQ) * ROWB + bColH;

    float acc[2][8][4];
#pragma unroll
    for (int mt = 0; mt < 2; mt++)
#pragma unroll
        for (int nt = 0; nt < 8; nt++)
#pragma unroll
            for (int e = 0; e < 4; e++) acc[mt][nt][e] = 0.f;

#pragma unroll
    for (int kc = 0; kc < NKC; kc++) {
        const uint32_t ko = kc * 32;          // 16 fp16 = 32 bytes per chunk
        uint32_t b[4][4];
#pragma unroll
        for (int q = 0; q < 4; q++) ldsm4(b[q], bAddr[q] + ko);
#pragma unroll
        for (int nt = 0; nt < 8; nt++) {
            const uint32_t b0 = b[nt >> 1][(nt & 1) * 2];
            const uint32_t b1 = b[nt >> 1][(nt & 1) * 2 + 1];
            mma16816(acc[0][nt], a0[kc], b0, b1);
            mma16816(acc[1][nt], a1[kc], b0, b1);
        }
    }

    // ---- epilogue: sum ex2 over all accumulator elements (mapping-free) ----
    float s0 = 0.f, s1 = 0.f, s2 = 0.f, s3 = 0.f;
#pragma unroll
    for (int mt = 0; mt < 2; mt++)
#pragma unroll
        for (int nt = 0; nt < 8; nt++) {
            s0 += ex2(acc[mt][nt][0]);
            s1 += ex2(acc[mt][nt][1]);
            s2 += ex2(acc[mt][nt][2]);
            s3 += ex2(acc[mt][nt][3]);
        }
    float tsum = (s0 + s1) + (s2 + s3);
#pragma unroll
    for (int off = 16; off; off >>= 1)
        tsum += __shfl_xor_sync(0xffffffffu, tsum, off);
    if (lane == 0) wsum[w] = tsum;
    __syncthreads();

    if (tid == 0) {
        double t = 0.0;
#pragma unroll
        for (int x = 0; x < 8; x++) t += (double)wsum[x];
        double wgt = (ti == tj) ? 1.0 : 2.0;
        double sgn = ((ti < TB / 2) == (tj < TB / 2)) ? 1.0 : -1.0;
        g_part[bid] = t * wgt * sgn;
    }
}

// ---------------------------------------------------------------------------
// Kernel 3: fixed-order double reduction -> scalar
// ---------------------------------------------------------------------------
__global__ void __launch_bounds__(512) finish_kernel(float* out) {
    __shared__ double s[512];
    const int tid = threadIdx.x;
    const double2* p2 = (const double2*)g_part;       // NBLK even
    double t0 = 0.0, t1 = 0.0;
#pragma unroll 4
    for (int i = tid; i < NBLK / 2; i += 512) {
        double2 v = p2[i];
        t0 += v.x;
        t1 += v.y;
    }
    s[tid] = t0 + t1;
    __syncthreads();
#pragma unroll
    for (int off = 256; off; off >>= 1) {
        if (tid < off) s[tid] += s[tid + off];
        __syncthreads();
    }
    if (tid == 0) out[0] = (float)(s[0] / 67108864.0);   // / n^2, n = 8192
}

// ---------------------------------------------------------------------------
extern "C" void kernel_launch(void* const* d_in, const int* in_sizes, int n_in,
                              void* d_out, int out_size) {
    const float* src = (const float*)d_in[0];
    const float* tgt = (const float*)d_in[1];

    const int smem_bytes = 2 * ATILEB;     // 36864 B
    cudaFuncSetAttribute(pair_kernel, cudaFuncAttributeMaxDynamicSharedMemorySize,
                         smem_bytes);

    split_kernel<<<(NP + 255) / 256, 256>>>(src, tgt);
    pair_kernel<<<NBLK, 256, smem_bytes>>>();
    finish_kernel<<<1, 512>>>((float*)d_out);
}

// round 10
// speedup vs baseline: 2.4613x; 1.1380x over previous
#include <cuda_runtime.h>
#include <cuda_fp16.h>
#include <math.h>
#include <stdint.h>

// ---------------------------------------------------------------------------
// MMD^2 (RBF, gamma=1), 8192x16 fp32, via mma.sync.m16n8k16 fp16 (sm_100 base).
//
// Coords scaled by sqrt(2*log2e), split x = hi + lo (fp16).
// K = 48: A chunks [hi | lo | hi], B chunks [hi | hi | lo]
//   => acc = dot_s(a,b) = 2*log2e*dot(a,b)     (lo*lo dropped, ~2^-22 rel)
// Norms folded in the epilogue via exp2(dot+na+nb) = exp2(dot)*ena*enb with
// ena/enb = exp2(-0.5|x_s|^2) precomputed per tile row in SMEM.
// Uses the documented m16n8k16 accumulator layout:
//   c0,c1 -> row gid,   cols 2*tig, 2*tig+1
//   c2,c3 -> row gid+8, cols 2*tig, 2*tig+1       (gid=lane>>2, tig=lane&3)
// Upper-triangle 128x128 tiles, weight 2 off-diagonal.
// ---------------------------------------------------------------------------

#define NSRC   8192
#define D      16
#define NP     16384
#define TILE   128
#define TB     (NP / TILE)                 // 128
#define NBLK   (TB * (TB + 1) / 2)         // 8256
#define SQ2L   1.6986436004918308f         // sqrt(2*log2(e))
#define ROWB   112                         // 96B data + 16B pad (conflict-free)
#define NKC    3                           // K = 48, chunks of 16
#define ATILEB (TILE * ROWB)               // 14336 B per tile side

// per point: u0,u1 = hi(16 fp16), u2,u3 = lo
__device__ uint4  g_S[NP * 4];
__device__ float  g_N[NP];                 // -0.5*|x_s|^2  (exp2-arg norm term)
__device__ double g_part[NBLK];

// ---------------- helpers ----------------
__device__ __forceinline__ float ex2(float x) {
    float r; asm("ex2.approx.f32 %0, %1;" : "=f"(r) : "f"(x)); return r;
}
__device__ __forceinline__ uint32_t smem_u32(const void* p) {
    uint32_t a;
    asm("{ .reg .u64 t; cvta.to.shared.u64 t, %1; cvt.u32.u64 %0, t; }"
        : "=r"(a) : "l"(p));
    return a;
}
__device__ __forceinline__ void ldsm4(uint32_t* r, uint32_t addr) {
    asm volatile("ldmatrix.sync.aligned.m8n8.x4.shared.b16 {%0,%1,%2,%3}, [%4];"
                 : "=r"(r[0]), "=r"(r[1]), "=r"(r[2]), "=r"(r[3]) : "r"(addr));
}
__device__ __forceinline__ void mma16816(float* c, const uint32_t* a,
                                         uint32_t b0, uint32_t b1) {
    asm volatile("mma.sync.aligned.m16n8k16.row.col.f32.f16.f16.f32 "
                 "{%0,%1,%2,%3}, {%4,%5,%6,%7}, {%8,%9}, {%0,%1,%2,%3};"
                 : "+f"(c[0]), "+f"(c[1]), "+f"(c[2]), "+f"(c[3])
                 : "r"(a[0]), "r"(a[1]), "r"(a[2]), "r"(a[3]), "r"(b0), "r"(b1));
}
__device__ __forceinline__ int tri_row_start(int t) {
    return t * TB - ((t * (t - 1)) >> 1);
}

// ---------------------------------------------------------------------------
// Kernel 1: scale, fp16 hi/lo split, norm term.
// ---------------------------------------------------------------------------
__global__ void __launch_bounds__(128) split_kernel(const float* __restrict__ src,
                                                    const float* __restrict__ tgt) {
    int p = blockIdx.x * 128 + threadIdx.x;
    if (p >= NP) return;
    const float* x = (p < NSRC) ? (src + (size_t)p * D) : (tgt + (size_t)(p - NSRC) * D);

    uint4 u[4];
    __half* hi = (__half*)&u[0];
    __half* lo = (__half*)&u[2];

    float ns = 0.f;
#pragma unroll
    for (int d = 0; d < D; d++) {
        float v = x[d] * SQ2L;
        ns = fmaf(v, v, ns);
        __half h = __float2half_rn(v);
        hi[d] = h;
        lo[d] = __float2half_rn(v - __half2float(h));
    }
    uint4* out = g_S + (size_t)p * 4;
#pragma unroll
    for (int i = 0; i < 4; i++) out[i] = u[i];
    g_N[p] = -0.5f * ns;
}

// ---------------------------------------------------------------------------
// Kernel 2: pairwise 128x128 tiles via fp16 mma.sync (K=48), epilogue norms.
// Warp w: rows (w&3)*32 + {0,16}, cols (w>>2)*64 (8 n8-tiles).
// ---------------------------------------------------------------------------
__global__ void __launch_bounds__(256, 2) pair_kernel() {
    extern __shared__ __align__(16) char dsm[];
    __shared__ float sLA[TILE];   // exp2(-0.5|a_s|^2) per A row
    __shared__ float sLB[TILE];   // exp2(-0.5|b_s|^2) per B row
    __shared__ float wsum[8];

    const int bid  = blockIdx.x;
    const int tid  = threadIdx.x;
    const int lane = tid & 31;
    const int w    = tid >> 5;

    int ti = (int)((2.0 * TB + 1.0 - sqrt((2.0 * TB + 1.0) * (2.0 * TB + 1.0)
                                          - 8.0 * (double)bid)) * 0.5);
    while (tri_row_start(ti + 1) <= bid) ti++;
    while (tri_row_start(ti) > bid) ti--;
    const int tj = ti + (bid - tri_row_start(ti));

    // ---- build A/B tiles in SMEM (row stride 112B; conflict-free ldmatrix) ----
    {
        const int  row = tid & 127;
        const bool isA = tid < 128;
        const int  pt  = (isA ? ti : tj) * TILE + row;
        const uint4* srow = g_S + (size_t)pt * 4;
        char* rbase = dsm + (isA ? 0 : ATILEB) + row * ROWB;

        uint4 u[4];
#pragma unroll
        for (int i = 0; i < 4; i++) u[i] = srow[i];

        // 16B chunk units (6 = 96B of K data):
        // A: [hi hi lo lo hi hi]    B: [hi hi hi hi lo lo]
        const int mapA[6] = {0,1, 2,3, 0,1};
        const int mapB[6] = {0,1, 0,1, 2,3};
#pragma unroll
        for (int c = 0; c < 6; c++) {
            int s = isA ? mapA[c] : mapB[c];
            *(uint4*)(rbase + c * 16) = u[s];
        }
        float e = ex2(g_N[pt]);
        if (isA) sLA[row] = e; else sLB[row] = e;
    }
    __syncthreads();

    const uint32_t sA = smem_u32(dsm);
    const uint32_t sB = sA + ATILEB;
    const int mbase = (w & 3) * 32;
    const int nbase = (w >> 2) * 64;

    // ---- preload all A fragments (3 kc x 2 m-tiles = 24 regs) ----
    const uint32_t aRow   = (uint32_t)(mbase + (lane & 7) + ((lane >> 3) & 1) * 8);
    const uint32_t aAddr0 = sA + aRow * ROWB + ((lane >> 4) & 1) * 16;
    const uint32_t aAddr1 = aAddr0 + 16 * ROWB;
    uint32_t a0[NKC][4], a1[NKC][4];
#pragma unroll
    for (int kc = 0; kc < NKC; kc++) {
        ldsm4(a0[kc], aAddr0 + kc * 32);
        ldsm4(a1[kc], aAddr1 + kc * 32);
    }

    const uint32_t bRowQ = (uint32_t)((lane & 7) + ((lane >> 4) & 1) * 8);
    const uint32_t bColH = ((lane >> 3) & 1) * 16;
    uint32_t bAddr[4];
#pragma unroll
    for (int q = 0; q < 4; q++)
        bAddr[q] = sB + (uint32_t)(nbase + 16 * q + bRowQ) * ROWB + bColH;

    float acc[2][8][4];
#pragma unroll
    for (int mt = 0; mt < 2; mt++)
#pragma unroll
        for (int nt = 0; nt < 8; nt++)
#pragma unroll
            for (int e = 0; e < 4; e++) acc[mt][nt][e] = 0.f;

#pragma unroll
    for (int kc = 0; kc < NKC; kc++) {
        const uint32_t ko = kc * 32;          // 16 fp16 = 32 bytes per chunk
        uint32_t b[4][4];
#pragma unroll
        for (int q = 0; q < 4; q++) ldsm4(b[q], bAddr[q] + ko);
#pragma unroll
        for (int nt = 0; nt < 8; nt++) {
            const uint32_t b0 = b[nt >> 1][(nt & 1) * 2];
            const uint32_t b1 = b[nt >> 1][(nt & 1) * 2 + 1];
            mma16816(acc[0][nt], a0[kc], b0, b1);
            mma16816(acc[1][nt], a1[kc], b0, b1);
        }
    }

    // ---- epilogue: k(a,b) = ex2(acc) * ena * enb; sum over tile ----
    const int gid = lane >> 2;
    const int tig = lane & 3;

    float ena[2][2];
#pragma unroll
    for (int mt = 0; mt < 2; mt++)
#pragma unroll
        for (int h = 0; h < 2; h++)
            ena[mt][h] = sLA[mbase + mt * 16 + gid + h * 8];

    float enb[8][2];
#pragma unroll
    for (int nt = 0; nt < 8; nt++) {
        int j0 = nbase + nt * 8 + tig * 2;
        enb[nt][0] = sLB[j0];
        enb[nt][1] = sLB[j0 + 1];
    }

    float p[2][2] = {{0.f, 0.f}, {0.f, 0.f}};
#pragma unroll
    for (int mt = 0; mt < 2; mt++)
#pragma unroll
        for (int nt = 0; nt < 8; nt++)
#pragma unroll
            for (int e = 0; e < 4; e++)
                p[mt][e >> 1] = fmaf(ex2(acc[mt][nt][e]), enb[nt][e & 1],
                                     p[mt][e >> 1]);

    float tsum = 0.f;
#pragma unroll
    for (int mt = 0; mt < 2; mt++)
#pragma unroll
        for (int h = 0; h < 2; h++)
            tsum = fmaf(p[mt][h], ena[mt][h], tsum);

#pragma unroll
    for (int off = 16; off; off >>= 1)
        tsum += __shfl_xor_sync(0xffffffffu, tsum, off);
    if (lane == 0) wsum[w] = tsum;
    __syncthreads();

    if (tid == 0) {
        double t = 0.0;
#pragma unroll
        for (int x = 0; x < 8; x++) t += (double)wsum[x];
        double wgt = (ti == tj) ? 1.0 : 2.0;
        double sgn = ((ti < TB / 2) == (tj < TB / 2)) ? 1.0 : -1.0;
        g_part[bid] = t * wgt * sgn;
    }
}

// ---------------------------------------------------------------------------
// Kernel 3: fixed-order double reduction -> scalar
// ---------------------------------------------------------------------------
__global__ void __launch_bounds__(512) finish_kernel(float* out) {
    __shared__ double s[512];
    const int tid = threadIdx.x;
    const double2* p2 = (const double2*)g_part;       // NBLK even
    double t0 = 0.0, t1 = 0.0;
#pragma unroll 4
    for (int i = tid; i < NBLK / 2; i += 512) {
        double2 v = p2[i];
        t0 += v.x;
        t1 += v.y;
    }
    s[tid] = t0 + t1;
    __syncthreads();
#pragma unroll
    for (int off = 256; off; off >>= 1) {
        if (tid < off) s[tid] += s[tid + off];
        __syncthreads();
    }
    if (tid == 0) out[0] = (float)(s[0] / 67108864.0);   // / n^2, n = 8192
}

// ---------------------------------------------------------------------------
extern "C" void kernel_launch(void* const* d_in, const int* in_sizes, int n_in,
                              void* d_out, int out_size) {
    const float* src = (const float*)d_in[0];
    const float* tgt = (const float*)d_in[1];

    const int smem_bytes = 2 * ATILEB;     // 28672 B
    cudaFuncSetAttribute(pair_kernel, cudaFuncAttributeMaxDynamicSharedMemorySize,
                         smem_bytes);

    split_kernel<<<NP / 128, 128>>>(src, tgt);
    pair_kernel<<<NBLK, 256, smem_bytes>>>();
    finish_kernel<<<1, 512>>>((float*)d_out);
}